// round 14
// baseline (speedup 1.0000x reference)
#include <cuda_runtime.h>
#include <cuda_fp16.h>
#include <cstdint>

// VQ nearest-codebook quantization, certified two-stage (R9):
//  stage1: hi-only mma.sync GEMM, packed-key top-2 fold; EXACT residual-norm
//          certificate (||x_lo||, max||c_lo|| computed exactly) -> ~3x fewer flags
//  fb:     3-pass split mma on compacted uncertified rows (exact decision)
//  finish: exact fp32 distance + codes gather (256-thread blocks)
// Inputs:  d_in[0]=z_e_x [65536,128] f32, d_in[1]=codebook [1024,128] f32
// Outputs (f32): codes [65536*128] | flat_idx [65536] | idx [65536] | dist [65536]

#define C_DIM 128
#define BM    128

// ---- stage-1 SMEM (bytes), 2 CTAs/SM ----
#define S1_CSQ   0          // 4096
#define S1_XSQ   4096       // 512
#define S1_XLO   4608       // 512 (||x_lo||^2 per row)
#define S1_SCAL  5120       // 2 f32: maxc, maxclo (norms)
#define S1_A_H   5248       // 32768 (128-aligned)
#define S1_B     38016      // 2 x 32768
#define S1_BBUF  32768
#define S1_SMEM  103552
// overlaid on B after mainloop:
#define S1_REDK1 S1_B               // 128*8 f32
#define S1_REDK2 (S1_B + 4096)      // 128*8 f32

// ---- fallback SMEM (bytes) ----
#define FB_RID   0
#define FB_A_H   512
#define FB_A_L   33280
#define FB_B     66048
#define FB_BBUF  65536
#define FB_SMEM  197120
#define FB_REDV  FB_B
#define FB_REDI  (FB_B + 4096)

__device__ uint4 g_B[8 * 4096];     // [8 chunks][hi 32KB | lo 32KB]
__device__ float g_csq[1024];
__device__ int   g_bi[65536];
__device__ int   g_list[65536];
__device__ int   g_nflag;
__device__ unsigned g_maxc_bits   = 0;   // max csq (bits; monotonic, replay-idempotent)
__device__ unsigned g_maxclo_bits = 0;   // max ||c_lo||^2 (bits)

// ---------------- helpers ----------------
__device__ __forceinline__ uint32_t smem_u32(const void* p) {
    uint32_t a;
    asm("{ .reg .u64 t; cvta.to.shared.u64 t, %1; cvt.u32.u64 %0, t; }" : "=r"(a) : "l"(p));
    return a;
}
__device__ __forceinline__ void ldsm_x4(uint32_t* r, uint32_t addr) {
    asm volatile("ldmatrix.sync.aligned.m8n8.x4.shared.b16 {%0,%1,%2,%3}, [%4];"
                 : "=r"(r[0]), "=r"(r[1]), "=r"(r[2]), "=r"(r[3]) : "r"(addr));
}
__device__ __forceinline__ void mma16816(float* c, const uint32_t* a, const uint32_t* b) {
    asm volatile("mma.sync.aligned.m16n8k16.row.col.f32.f16.f16.f32 "
                 "{%0,%1,%2,%3}, {%4,%5,%6,%7}, {%8,%9}, {%0,%1,%2,%3};"
                 : "+f"(c[0]), "+f"(c[1]), "+f"(c[2]), "+f"(c[3])
                 : "r"(a[0]), "r"(a[1]), "r"(a[2]), "r"(a[3]), "r"(b[0]), "r"(b[1]));
}
#define CP_ASYNC16(dst, src) \
    asm volatile("cp.async.cg.shared.global [%0], [%1], 16;" :: "r"(dst), "l"(src))
#define CP_COMMIT() asm volatile("cp.async.commit_group;" ::: "memory")
#define CP_WAIT1()  asm volatile("cp.async.wait_group 1;" ::: "memory")
#define CP_WAIT0()  asm volatile("cp.async.wait_group 0;" ::: "memory")

__device__ __forceinline__ void split2(float a, float b, uint32_t& hi, uint32_t& lo) {
    __half2 h = __floats2half2_rn(a, b);
    float2  f = __half22float2(h);
    __half2 l = __floats2half2_rn(a - f.x, b - f.y);
    hi = *reinterpret_cast<uint32_t*>(&h);
    lo = *reinterpret_cast<uint32_t*>(&l);
}
__device__ __forceinline__ float packkey(float v, uint32_t code) {
    return __uint_as_float((__float_as_uint(v) & 0xFFFFFC00u) | code);
}

// ---------------- prep: split codebook, csq, residual norms ----------------
__global__ void prep_cb(const float* __restrict__ CB) {
    int t = blockIdx.x * blockDim.x + threadIdx.x;   // 0..2047
    if (t == 0) g_nflag = 0;
    int code = t >> 1, h = t & 1;
    const float4* src = reinterpret_cast<const float4*>(CB + (size_t)code * C_DIM + h * 64);
    char* base = (char*)g_B + (size_t)(code >> 7) * 65536;
    int r = code & 127;
    float s = 0.f, slo = 0.f;
    #pragma unroll
    for (int q = 0; q < 16; q += 2) {
        float4 v0 = src[q], v1 = src[q + 1];
        s += v0.x*v0.x + v0.y*v0.y + v0.z*v0.z + v0.w*v0.w
           + v1.x*v1.x + v1.y*v1.y + v1.z*v1.z + v1.w*v1.w;
        uint4 H, L;
        split2(v0.x, v0.y, H.x, L.x); split2(v0.z, v0.w, H.y, L.y);
        split2(v1.x, v1.y, H.z, L.z); split2(v1.z, v1.w, H.w, L.w);
        // exact lo-residual: a - (float)rn16(a)
        {
            float2 f0 = __half22float2(*reinterpret_cast<__half2*>(&H.x));
            float2 f1 = __half22float2(*reinterpret_cast<__half2*>(&H.y));
            float2 f2 = __half22float2(*reinterpret_cast<__half2*>(&H.z));
            float2 f3 = __half22float2(*reinterpret_cast<__half2*>(&H.w));
            float d;
            d = v0.x - f0.x; slo += d * d;  d = v0.y - f0.y; slo += d * d;
            d = v0.z - f1.x; slo += d * d;  d = v0.w - f1.y; slo += d * d;
            d = v1.x - f2.x; slo += d * d;  d = v1.y - f2.y; slo += d * d;
            d = v1.z - f3.x; slo += d * d;  d = v1.w - f3.y; slo += d * d;
        }
        int cg = h * 8 + (q >> 1);
        uint32_t off = (uint32_t)(r * 256 + ((cg ^ (r & 7)) << 4));
        *reinterpret_cast<uint4*>(base + off) = H;
        *reinterpret_cast<uint4*>(base + 32768 + off) = L;
    }
    s   += __shfl_xor_sync(0xffffffffu, s, 1);
    slo += __shfl_xor_sync(0xffffffffu, slo, 1);
    if (!h) {
        g_csq[code] = s;
        atomicMax(&g_maxc_bits,   __float_as_uint(s));     // positive floats: bit order = value order
        atomicMax(&g_maxclo_bits, __float_as_uint(slo));
    }
}

// ---------------- stage 1 ----------------
__device__ __forceinline__ void s1_issue(uint32_t sb, int buf, int chunk, int tid) {
    const char* src = (const char*)g_B + (size_t)chunk * 65536 + tid * 16;  // hi half
    uint32_t dst = sb + S1_B + buf * S1_BBUF + tid * 16;
    #pragma unroll
    for (int i = 0; i < 8; i++)
        CP_ASYNC16(dst + i * 4096, src + i * 4096);
}

__global__ __launch_bounds__(256, 2)
void vq_stage1(const float* __restrict__ X, int n_codes)
{
    extern __shared__ char smem[];
    const uint32_t sb = smem_u32(smem);
    const int tid = threadIdx.x, lane = tid & 31, wid = tid >> 5;
    const int warpM = wid >> 1, warpN = wid & 1;      // 4x2 grid, 32x64 tiles
    const int block_row = blockIdx.x * BM;
    const int NC = n_codes >> 7;

    s1_issue(sb, 0, 0, tid);
    CP_COMMIT();

    for (int i = tid; i < n_codes; i += 256)
        reinterpret_cast<float*>(smem + S1_CSQ)[i] = g_csq[i];
    if (tid == 0) {
        reinterpret_cast<float*>(smem + S1_SCAL)[0] = sqrtf(__uint_as_float(g_maxc_bits));
        reinterpret_cast<float*>(smem + S1_SCAL)[1] = sqrtf(__uint_as_float(g_maxclo_bits));
    }

    // A hi tile + fused xsq and exact ||x_lo||^2 (2 threads/row)
    {
        const int r = tid >> 1, h = tid & 1;
        const float4* src = reinterpret_cast<const float4*>(
            X + (size_t)(block_row + r) * C_DIM + h * 64);
        float s = 0.f, slo = 0.f;
        #pragma unroll
        for (int q = 0; q < 16; q += 2) {
            float4 v0 = src[q], v1 = src[q + 1];
            s += v0.x*v0.x + v0.y*v0.y + v0.z*v0.z + v0.w*v0.w
               + v1.x*v1.x + v1.y*v1.y + v1.z*v1.z + v1.w*v1.w;
            uint4 H;
            __half2 h0 = __floats2half2_rn(v0.x, v0.y), h1 = __floats2half2_rn(v0.z, v0.w);
            __half2 h2 = __floats2half2_rn(v1.x, v1.y), h3 = __floats2half2_rn(v1.z, v1.w);
            H.x = *reinterpret_cast<uint32_t*>(&h0); H.y = *reinterpret_cast<uint32_t*>(&h1);
            H.z = *reinterpret_cast<uint32_t*>(&h2); H.w = *reinterpret_cast<uint32_t*>(&h3);
            {
                float2 f0 = __half22float2(h0), f1 = __half22float2(h1);
                float2 f2 = __half22float2(h2), f3 = __half22float2(h3);
                float d;
                d = v0.x - f0.x; slo += d * d;  d = v0.y - f0.y; slo += d * d;
                d = v0.z - f1.x; slo += d * d;  d = v0.w - f1.y; slo += d * d;
                d = v1.x - f2.x; slo += d * d;  d = v1.y - f2.y; slo += d * d;
                d = v1.z - f3.x; slo += d * d;  d = v1.w - f3.y; slo += d * d;
            }
            int cg = h * 8 + (q >> 1);
            uint32_t off = (uint32_t)(r * 256 + ((cg ^ (r & 7)) << 4));
            *reinterpret_cast<uint4*>(smem + S1_A_H + off) = H;
        }
        s   += __shfl_xor_sync(0xffffffffu, s, 1);
        slo += __shfl_xor_sync(0xffffffffu, slo, 1);
        if (!h) {
            reinterpret_cast<float*>(smem + S1_XSQ)[r] = s;
            reinterpret_cast<float*>(smem + S1_XLO)[r] = slo;
        }
    }

    if (NC > 1) s1_issue(sb, 1, 1, tid);
    CP_COMMIT();
    __syncthreads();

    const uint32_t aOff   = (uint32_t)((warpM * 32 + (lane & 15)) * 256);
    const uint32_t bOff   = (uint32_t)((warpN * 64 + (lane & 7) + ((lane >> 4) << 3)) * 256);
    const uint32_t sw     = (uint32_t)(lane & 7);
    const uint32_t achsel = (uint32_t)(lane >> 4);
    const uint32_t bchsel = (uint32_t)((lane >> 3) & 1);

    const float INF = __int_as_float(0x7F800000);
    float k1[4], k2[4];
    #pragma unroll
    for (int i = 0; i < 4; i++) { k1[i] = INF; k2[i] = INF; }

    for (int c = 0; c < NC; c++) {
        CP_WAIT1();
        __syncthreads();
        const int buf = c & 1;
        float acc[2][8][4];
        #pragma unroll
        for (int mi = 0; mi < 2; mi++)
            #pragma unroll
            for (int ni = 0; ni < 8; ni++)
                #pragma unroll
                for (int j = 0; j < 4; j++) acc[mi][ni][j] = 0.f;

        const uint32_t Ab = sb + S1_A_H + aOff;
        const uint32_t Bb = sb + S1_B + buf * S1_BBUF + bOff;
        #pragma unroll
        for (int ks = 0; ks < 8; ks++) {
            const uint32_t ach = (((uint32_t)(2 * ks) + achsel) ^ sw) << 4;
            const uint32_t bch = (((uint32_t)(2 * ks) + bchsel) ^ sw) << 4;
            uint32_t a[2][4];
            ldsm_x4(a[0], Ab + ach);
            ldsm_x4(a[1], Ab + 4096 + ach);
            #pragma unroll
            for (int h = 0; h < 2; h++) {
                uint32_t b[2][4];
                ldsm_x4(b[0], Bb + (h * 2 + 0) * 4096 + bch);
                ldsm_x4(b[1], Bb + (h * 2 + 1) * 4096 + bch);
                #pragma unroll
                for (int mi = 0; mi < 2; mi++)
                    #pragma unroll
                    for (int s2 = 0; s2 < 4; s2++)
                        mma16816(acc[mi][h * 4 + s2], a[mi], &b[s2 >> 1][(s2 & 1) * 2]);
            }
        }

        {   // packed-key top-2 fold
            const float* csqs = reinterpret_cast<const float*>(smem + S1_CSQ)
                                + c * 128 + warpN * 64;
            const uint32_t cb = (uint32_t)(c * 128 + warpN * 64 + (lane & 3) * 2);
            #pragma unroll
            for (int ni = 0; ni < 8; ni++) {
                const int col = ni * 8 + (lane & 3) * 2;
                const float cs0 = csqs[col], cs1 = csqs[col + 1];
                const uint32_t code0 = cb + ni * 8, code1 = code0 + 1;
                #pragma unroll
                for (int mi = 0; mi < 2; mi++)
                    #pragma unroll
                    for (int rh = 0; rh < 2; rh++) {
                        const int p = mi * 2 + rh;
                        float f0 = packkey(fmaf(-2.f, acc[mi][ni][rh * 2],     cs0), code0);
                        float f1 = packkey(fmaf(-2.f, acc[mi][ni][rh * 2 + 1], cs1), code1);
                        float m0 = fminf(k1[p], f0);
                        k2[p] = fminf(fmaxf(k1[p], f0), k2[p]);
                        k1[p] = m0;
                        float m1 = fminf(k1[p], f1);
                        k2[p] = fminf(fmaxf(k1[p], f1), k2[p]);
                        k1[p] = m1;
                    }
            }
        }

        __syncthreads();
        if (c + 2 < NC) s1_issue(sb, buf, c + 2, tid);
        CP_COMMIT();
    }

    CP_WAIT0();
    __syncthreads();

    #pragma unroll
    for (int mi = 0; mi < 2; mi++)
        #pragma unroll
        for (int rh = 0; rh < 2; rh++) {
            const int rowl = warpM * 32 + mi * 16 + rh * 8 + (lane >> 2);
            const int slot = warpN * 4 + (lane & 3);
            reinterpret_cast<float*>(smem + S1_REDK1)[rowl * 8 + slot] = k1[mi * 2 + rh];
            reinterpret_cast<float*>(smem + S1_REDK2)[rowl * 8 + slot] = k2[mi * 2 + rh];
        }
    __syncthreads();

    if (tid < BM) {
        const float* r1 = reinterpret_cast<const float*>(smem + S1_REDK1) + tid * 8;
        const float* r2 = reinterpret_cast<const float*>(smem + S1_REDK2) + tid * 8;
        float K1 = r1[0], K2 = r2[0];
        #pragma unroll
        for (int s = 1; s < 8; s++) {
            float a1 = r1[s], a2 = r2[s];
            float n1 = fminf(K1, a1);
            K2 = fminf(fminf(K2, a2), fmaxf(K1, a1));
            K1 = n1;
        }
        const int bi = (int)(__float_as_uint(K1) & 1023u);
        const int row = block_row + tid;
        const float xsqv   = reinterpret_cast<float*>(smem + S1_XSQ)[tid];
        const float xlosq  = reinterpret_cast<float*>(smem + S1_XLO)[tid];
        const float maxc   = reinterpret_cast<float*>(smem + S1_SCAL)[0];
        const float maxclo = reinterpret_cast<float*>(smem + S1_SCAL)[1];
        // exact-norm Cauchy-Schwarz certificate:
        //   per-score err <= 2(||x_lo||*||c|| + ||x_h||*||c_lo||); gap uses 2 scores
        const float xlo = sqrtf(xlosq);
        const float xh  = sqrtf(xsqv) + xlo;
        float analog = 4.f * (xlo * maxc + xh * maxclo);
        float pert   = 2.5e-4f * (fabsf(K1) + fabsf(K2)) + 0.03f;  // key-mask + accum slack
        float thresh = analog * 1.05f + pert;
        g_bi[row] = bi;
        if ((K2 - K1) <= thresh) {
            int pos = atomicAdd(&g_nflag, 1);
            g_list[pos] = row;
        }
    }
}

// ---------------- fallback: 3-pass split mma, 128 rows per tile ----------------
__device__ __forceinline__ void fb_issue(uint32_t sb, int buf, int chunk, int tid) {
    const char* src = (const char*)g_B + (size_t)chunk * 65536 + tid * 16;  // hi+lo
    uint32_t dst = sb + FB_B + buf * FB_BBUF + tid * 16;
    #pragma unroll
    for (int i = 0; i < 16; i++)
        CP_ASYNC16(dst + i * 4096, src + i * 4096);
}

__global__ __launch_bounds__(256, 1)
void vq_fb(const float* __restrict__ X, int n_codes)
{
    extern __shared__ char smem[];
    const uint32_t sb = smem_u32(smem);
    const int tid = threadIdx.x, lane = tid & 31, wid = tid >> 5;
    const int warpM = wid >> 1, warpN = wid & 1;      // 4x2 grid, 32x64 tiles
    const int NC = n_codes >> 7;
    const int Nf = g_nflag;

    for (int tile = blockIdx.x; tile * 128 < Nf; tile += gridDim.x) {
        CP_WAIT0();
        __syncthreads();
        if (tid < 128) {
            int idx = tile * 128 + tid;
            reinterpret_cast<int*>(smem + FB_RID)[tid] = g_list[idx < Nf ? idx : Nf - 1];
        }
        __syncthreads();

        {
            const int j = tid >> 1, h = tid & 1;
            const int srow = reinterpret_cast<int*>(smem + FB_RID)[j];
            const float4* src = reinterpret_cast<const float4*>(
                X + (size_t)srow * C_DIM + h * 64);
            #pragma unroll
            for (int q = 0; q < 16; q += 2) {
                float4 v0 = src[q], v1 = src[q + 1];
                uint4 H, L;
                split2(v0.x, v0.y, H.x, L.x); split2(v0.z, v0.w, H.y, L.y);
                split2(v1.x, v1.y, H.z, L.z); split2(v1.z, v1.w, H.w, L.w);
                int cg = h * 8 + (q >> 1);
                uint32_t off = (uint32_t)(j * 256 + ((cg ^ (j & 7)) << 4));
                *reinterpret_cast<uint4*>(smem + FB_A_H + off) = H;
                *reinterpret_cast<uint4*>(smem + FB_A_L + off) = L;
            }
        }
        __syncthreads();

        fb_issue(sb, 0, 0, tid);  CP_COMMIT();
        fb_issue(sb, 1, 1, tid);  CP_COMMIT();

        const uint32_t aOff   = (uint32_t)((warpM * 32 + (lane & 15)) * 256);
        const uint32_t bOff   = (uint32_t)((warpN * 64 + (lane & 7) + ((lane >> 4) << 3)) * 256);
        const uint32_t sw     = (uint32_t)(lane & 7);
        const uint32_t achsel = (uint32_t)(lane >> 4);
        const uint32_t bchsel = (uint32_t)((lane >> 3) & 1);

        float bestv[4];
        int   besti[4];
        #pragma unroll
        for (int i = 0; i < 4; i++) { bestv[i] = 3.4e38f; besti[i] = 0; }

        for (int c = 0; c < NC; c++) {
            CP_WAIT1();
            __syncthreads();
            const int buf = c & 1;
            float acc[2][8][4];
            #pragma unroll
            for (int mi = 0; mi < 2; mi++)
                #pragma unroll
                for (int ni = 0; ni < 8; ni++)
                    #pragma unroll
                    for (int j2 = 0; j2 < 4; j2++) acc[mi][ni][j2] = 0.f;

            #pragma unroll
            for (int pass = 0; pass < 3; pass++) {
                const uint32_t Ab = sb + (pass == 2 ? FB_A_L : FB_A_H) + aOff;
                const uint32_t Bb = sb + FB_B + buf * FB_BBUF + (pass == 1 ? 32768 : 0) + bOff;
                #pragma unroll
                for (int ks = 0; ks < 8; ks++) {
                    const uint32_t ach = (((uint32_t)(2 * ks) + achsel) ^ sw) << 4;
                    const uint32_t bch = (((uint32_t)(2 * ks) + bchsel) ^ sw) << 4;
                    uint32_t a[2][4], b[4][4];
                    ldsm_x4(a[0], Ab + ach);
                    ldsm_x4(a[1], Ab + 4096 + ach);
                    #pragma unroll
                    for (int nf2 = 0; nf2 < 4; nf2++)
                        ldsm_x4(b[nf2], Bb + nf2 * 4096 + bch);
                    #pragma unroll
                    for (int mi = 0; mi < 2; mi++)
                        #pragma unroll
                        for (int ni = 0; ni < 8; ni++)
                            mma16816(acc[mi][ni], a[mi], &b[ni >> 1][(ni & 1) * 2]);
                }
            }

            #pragma unroll
            for (int mi = 0; mi < 2; mi++)
                #pragma unroll
                for (int ni = 0; ni < 8; ni++) {
                    const int col = ni * 8 + (lane & 3) * 2;
                    const int gcol = c * 128 + warpN * 64 + col;
                    const float cs0 = __ldg(&g_csq[gcol]), cs1 = __ldg(&g_csq[gcol + 1]);
                    #pragma unroll
                    for (int rh = 0; rh < 2; rh++) {
                        const int p = mi * 2 + rh;
                        float v0 = fmaf(-2.f, acc[mi][ni][rh * 2],     cs0);
                        float v1 = fmaf(-2.f, acc[mi][ni][rh * 2 + 1], cs1);
                        if (v0 < bestv[p]) { bestv[p] = v0; besti[p] = gcol; }
                        if (v1 < bestv[p]) { bestv[p] = v1; besti[p] = gcol + 1; }
                    }
                }

            __syncthreads();
            if (c + 2 < NC) fb_issue(sb, buf, c + 2, tid);
            CP_COMMIT();
        }

        CP_WAIT0();
        __syncthreads();

        #pragma unroll
        for (int mi = 0; mi < 2; mi++)
            #pragma unroll
            for (int rh = 0; rh < 2; rh++) {
                const int rowl = warpM * 32 + mi * 16 + rh * 8 + (lane >> 2);
                const int slot = warpN * 4 + (lane & 3);
                reinterpret_cast<float*>(smem + FB_REDV)[rowl * 8 + slot] = bestv[mi * 2 + rh];
                reinterpret_cast<int*>(smem + FB_REDI)[rowl * 8 + slot]   = besti[mi * 2 + rh];
            }
        __syncthreads();

        if (tid < 128) {
            const float* rv = reinterpret_cast<const float*>(smem + FB_REDV) + tid * 8;
            const int*   ri = reinterpret_cast<const int*>(smem + FB_REDI) + tid * 8;
            float bv = rv[0]; int bi = ri[0];
            #pragma unroll
            for (int s = 1; s < 8; s++) {
                float v = rv[s]; int ii = ri[s];
                if (v < bv || (v == bv && ii < bi)) { bv = v; bi = ii; }
            }
            g_bi[reinterpret_cast<int*>(smem + FB_RID)[tid]] = bi;
        }
        __syncthreads();
    }
}

// ---------------- finish: exact fp32 distances + gather ----------------
__global__ __launch_bounds__(256, 4)
void vq_finish(const float* __restrict__ X, const float* __restrict__ CB,
               float* __restrict__ out_codes, float* __restrict__ out_fidx,
               float* __restrict__ out_idx,   float* __restrict__ out_dist)
{
    const int warp = threadIdx.x >> 5, lane = threadIdx.x & 31;
    const int row = blockIdx.x * 8 + warp;

    const int bi = g_bi[row];
    float4 xv = reinterpret_cast<const float4*>(X + (size_t)row * C_DIM)[lane];
    float4 cv = reinterpret_cast<const float4*>(CB + (size_t)bi * C_DIM)[lane];

    float xsq = xv.x*xv.x + xv.y*xv.y + xv.z*xv.z + xv.w*xv.w;
    float dot = cv.x*xv.x + cv.y*xv.y + cv.z*xv.z + cv.w*xv.w;
    #pragma unroll
    for (int o = 16; o; o >>= 1) {
        xsq += __shfl_xor_sync(0xffffffffu, xsq, o);
        dot += __shfl_xor_sync(0xffffffffu, dot, o);
    }

    if (lane == 0 && out_fidx) {
        float fbi = (float)bi;
        out_fidx[row] = fbi;
        out_idx[row]  = fbi;
        out_dist[row] = xsq + fmaf(-2.f, dot, g_csq[bi]);
    }
    reinterpret_cast<float4*>(out_codes + (size_t)row * C_DIM)[lane] = cv;
}

extern "C" void kernel_launch(void* const* d_in, const int* in_sizes, int n_in,
                              void* d_out, int out_size)
{
    const float* X  = (const float*)d_in[0];
    const float* CB = (const float*)d_in[1];
    float* out = (float*)d_out;

    const int n_rows  = in_sizes[0] / C_DIM;   // 65536
    const int n_codes = in_sizes[1] / C_DIM;   // 1024

    size_t codes_n = (size_t)n_rows * C_DIM;
    bool extras = ((size_t)out_size >= codes_n + 3 * (size_t)n_rows);

    float* out_codes = out;
    float* out_fidx  = extras ? out + codes_n : nullptr;
    float* out_idx   = extras ? out + codes_n + n_rows : nullptr;
    float* out_dist  = extras ? out + codes_n + 2 * (size_t)n_rows : nullptr;

    static bool attr_set = false;
    if (!attr_set) {
        cudaFuncSetAttribute(vq_stage1, cudaFuncAttributeMaxDynamicSharedMemorySize, S1_SMEM);
        cudaFuncSetAttribute(vq_fb,     cudaFuncAttributeMaxDynamicSharedMemorySize, FB_SMEM);
        attr_set = true;
    }

    prep_cb<<<(n_codes * 2) / 256, 256>>>(CB);
    vq_stage1<<<n_rows / BM, 256, S1_SMEM>>>(X, n_codes);
    vq_fb<<<64, 256, FB_SMEM>>>(X, n_codes);
    vq_finish<<<n_rows / 8, 256>>>(X, CB, out_codes, out_fidx, out_idx, out_dist);
}

// round 15
// speedup vs baseline: 1.5485x; 1.5485x over previous
#include <cuda_runtime.h>
#include <cuda_fp16.h>
#include <cstdint>

// VQ nearest-codebook quantization, certified two-stage (R9):
//  stage1: hi-only mma.sync GEMM, packed-key top-2 fold; EXACT residual-norm
//          certificate (||x_lo||, max||c_lo|| computed exactly) -> ~3x fewer flags
//  fb:     3-pass split mma on compacted uncertified rows (exact decision)
//  finish: exact fp32 distance + codes gather (256-thread blocks)
// Inputs:  d_in[0]=z_e_x [65536,128] f32, d_in[1]=codebook [1024,128] f32
// Outputs (f32): codes [65536*128] | flat_idx [65536] | idx [65536] | dist [65536]

#define C_DIM 128
#define BM    128

// ---- stage-1 SMEM (bytes), 2 CTAs/SM ----
#define S1_CSQ   0          // 4096
#define S1_XSQ   4096       // 512
#define S1_XLO   4608       // 512 (||x_lo||^2 per row)
#define S1_SCAL  5120       // 2 f32: maxc, maxclo (norms)
#define S1_A_H   5248       // 32768 (128-aligned)
#define S1_B     38016      // 2 x 32768
#define S1_BBUF  32768
#define S1_SMEM  103552
// overlaid on B after mainloop:
#define S1_REDK1 S1_B               // 128*8 f32
#define S1_REDK2 (S1_B + 4096)      // 128*8 f32

// ---- fallback SMEM (bytes) ----
#define FB_RID   0
#define FB_A_H   512
#define FB_A_L   33280
#define FB_B     66048
#define FB_BBUF  65536
#define FB_SMEM  197120
#define FB_REDV  FB_B
#define FB_REDI  (FB_B + 4096)

__device__ uint4 g_B[8 * 4096];     // [8 chunks][hi 32KB | lo 32KB]
__device__ float g_csq[1024];
__device__ int   g_bi[65536];
__device__ int   g_list[65536];
__device__ int   g_nflag;
__device__ unsigned g_maxc_bits   = 0;   // max csq (bits; monotonic, replay-idempotent)
__device__ unsigned g_maxclo_bits = 0;   // max ||c_lo||^2 (bits)

// ---------------- helpers ----------------
__device__ __forceinline__ uint32_t smem_u32(const void* p) {
    uint32_t a;
    asm("{ .reg .u64 t; cvta.to.shared.u64 t, %1; cvt.u32.u64 %0, t; }" : "=r"(a) : "l"(p));
    return a;
}
__device__ __forceinline__ void ldsm_x4(uint32_t* r, uint32_t addr) {
    asm volatile("ldmatrix.sync.aligned.m8n8.x4.shared.b16 {%0,%1,%2,%3}, [%4];"
                 : "=r"(r[0]), "=r"(r[1]), "=r"(r[2]), "=r"(r[3]) : "r"(addr));
}
__device__ __forceinline__ void mma16816(float* c, const uint32_t* a, const uint32_t* b) {
    asm volatile("mma.sync.aligned.m16n8k16.row.col.f32.f16.f16.f32 "
                 "{%0,%1,%2,%3}, {%4,%5,%6,%7}, {%8,%9}, {%0,%1,%2,%3};"
                 : "+f"(c[0]), "+f"(c[1]), "+f"(c[2]), "+f"(c[3])
                 : "r"(a[0]), "r"(a[1]), "r"(a[2]), "r"(a[3]), "r"(b[0]), "r"(b[1]));
}
#define CP_ASYNC16(dst, src) \
    asm volatile("cp.async.cg.shared.global [%0], [%1], 16;" :: "r"(dst), "l"(src))
#define CP_COMMIT() asm volatile("cp.async.commit_group;" ::: "memory")
#define CP_WAIT1()  asm volatile("cp.async.wait_group 1;" ::: "memory")
#define CP_WAIT0()  asm volatile("cp.async.wait_group 0;" ::: "memory")

__device__ __forceinline__ void split2(float a, float b, uint32_t& hi, uint32_t& lo) {
    __half2 h = __floats2half2_rn(a, b);
    float2  f = __half22float2(h);
    __half2 l = __floats2half2_rn(a - f.x, b - f.y);
    hi = *reinterpret_cast<uint32_t*>(&h);
    lo = *reinterpret_cast<uint32_t*>(&l);
}
__device__ __forceinline__ float packkey(float v, uint32_t code) {
    return __uint_as_float((__float_as_uint(v) & 0xFFFFFC00u) | code);
}

// ---------------- prep: split codebook, csq, residual norms ----------------
__global__ void prep_cb(const float* __restrict__ CB) {
    int t = blockIdx.x * blockDim.x + threadIdx.x;   // 0..2047
    if (t == 0) g_nflag = 0;
    int code = t >> 1, h = t & 1;
    const float4* src = reinterpret_cast<const float4*>(CB + (size_t)code * C_DIM + h * 64);
    char* base = (char*)g_B + (size_t)(code >> 7) * 65536;
    int r = code & 127;
    float s = 0.f, slo = 0.f;
    #pragma unroll
    for (int q = 0; q < 16; q += 2) {
        float4 v0 = src[q], v1 = src[q + 1];
        s += v0.x*v0.x + v0.y*v0.y + v0.z*v0.z + v0.w*v0.w
           + v1.x*v1.x + v1.y*v1.y + v1.z*v1.z + v1.w*v1.w;
        uint4 H, L;
        split2(v0.x, v0.y, H.x, L.x); split2(v0.z, v0.w, H.y, L.y);
        split2(v1.x, v1.y, H.z, L.z); split2(v1.z, v1.w, H.w, L.w);
        // exact lo-residual: a - (float)rn16(a)
        {
            float2 f0 = __half22float2(*reinterpret_cast<__half2*>(&H.x));
            float2 f1 = __half22float2(*reinterpret_cast<__half2*>(&H.y));
            float2 f2 = __half22float2(*reinterpret_cast<__half2*>(&H.z));
            float2 f3 = __half22float2(*reinterpret_cast<__half2*>(&H.w));
            float d;
            d = v0.x - f0.x; slo += d * d;  d = v0.y - f0.y; slo += d * d;
            d = v0.z - f1.x; slo += d * d;  d = v0.w - f1.y; slo += d * d;
            d = v1.x - f2.x; slo += d * d;  d = v1.y - f2.y; slo += d * d;
            d = v1.z - f3.x; slo += d * d;  d = v1.w - f3.y; slo += d * d;
        }
        int cg = h * 8 + (q >> 1);
        uint32_t off = (uint32_t)(r * 256 + ((cg ^ (r & 7)) << 4));
        *reinterpret_cast<uint4*>(base + off) = H;
        *reinterpret_cast<uint4*>(base + 32768 + off) = L;
    }
    s   += __shfl_xor_sync(0xffffffffu, s, 1);
    slo += __shfl_xor_sync(0xffffffffu, slo, 1);
    if (!h) {
        g_csq[code] = s;
        atomicMax(&g_maxc_bits,   __float_as_uint(s));     // positive floats: bit order = value order
        atomicMax(&g_maxclo_bits, __float_as_uint(slo));
    }
}

// ---------------- stage 1 ----------------
__device__ __forceinline__ void s1_issue(uint32_t sb, int buf, int chunk, int tid) {
    const char* src = (const char*)g_B + (size_t)chunk * 65536 + tid * 16;  // hi half
    uint32_t dst = sb + S1_B + buf * S1_BBUF + tid * 16;
    #pragma unroll
    for (int i = 0; i < 8; i++)
        CP_ASYNC16(dst + i * 4096, src + i * 4096);
}

__global__ __launch_bounds__(256, 2)
void vq_stage1(const float* __restrict__ X, int n_codes)
{
    extern __shared__ char smem[];
    const uint32_t sb = smem_u32(smem);
    const int tid = threadIdx.x, lane = tid & 31, wid = tid >> 5;
    const int warpM = wid >> 1, warpN = wid & 1;      // 4x2 grid, 32x64 tiles
    const int block_row = blockIdx.x * BM;
    const int NC = n_codes >> 7;

    s1_issue(sb, 0, 0, tid);
    CP_COMMIT();

    for (int i = tid; i < n_codes; i += 256)
        reinterpret_cast<float*>(smem + S1_CSQ)[i] = g_csq[i];
    if (tid == 0) {
        reinterpret_cast<float*>(smem + S1_SCAL)[0] = sqrtf(__uint_as_float(g_maxc_bits));
        reinterpret_cast<float*>(smem + S1_SCAL)[1] = sqrtf(__uint_as_float(g_maxclo_bits));
    }

    // A hi tile + fused xsq and exact ||x_lo||^2 (2 threads/row)
    {
        const int r = tid >> 1, h = tid & 1;
        const float4* src = reinterpret_cast<const float4*>(
            X + (size_t)(block_row + r) * C_DIM + h * 64);
        float s = 0.f, slo = 0.f;
        #pragma unroll
        for (int q = 0; q < 16; q += 2) {
            float4 v0 = src[q], v1 = src[q + 1];
            s += v0.x*v0.x + v0.y*v0.y + v0.z*v0.z + v0.w*v0.w
               + v1.x*v1.x + v1.y*v1.y + v1.z*v1.z + v1.w*v1.w;
            uint4 H;
            __half2 h0 = __floats2half2_rn(v0.x, v0.y), h1 = __floats2half2_rn(v0.z, v0.w);
            __half2 h2 = __floats2half2_rn(v1.x, v1.y), h3 = __floats2half2_rn(v1.z, v1.w);
            H.x = *reinterpret_cast<uint32_t*>(&h0); H.y = *reinterpret_cast<uint32_t*>(&h1);
            H.z = *reinterpret_cast<uint32_t*>(&h2); H.w = *reinterpret_cast<uint32_t*>(&h3);
            {
                float2 f0 = __half22float2(h0), f1 = __half22float2(h1);
                float2 f2 = __half22float2(h2), f3 = __half22float2(h3);
                float d;
                d = v0.x - f0.x; slo += d * d;  d = v0.y - f0.y; slo += d * d;
                d = v0.z - f1.x; slo += d * d;  d = v0.w - f1.y; slo += d * d;
                d = v1.x - f2.x; slo += d * d;  d = v1.y - f2.y; slo += d * d;
                d = v1.z - f3.x; slo += d * d;  d = v1.w - f3.y; slo += d * d;
            }
            int cg = h * 8 + (q >> 1);
            uint32_t off = (uint32_t)(r * 256 + ((cg ^ (r & 7)) << 4));
            *reinterpret_cast<uint4*>(smem + S1_A_H + off) = H;
        }
        s   += __shfl_xor_sync(0xffffffffu, s, 1);
        slo += __shfl_xor_sync(0xffffffffu, slo, 1);
        if (!h) {
            reinterpret_cast<float*>(smem + S1_XSQ)[r] = s;
            reinterpret_cast<float*>(smem + S1_XLO)[r] = slo;
        }
    }

    if (NC > 1) s1_issue(sb, 1, 1, tid);
    CP_COMMIT();
    __syncthreads();

    const uint32_t aOff   = (uint32_t)((warpM * 32 + (lane & 15)) * 256);
    const uint32_t bOff   = (uint32_t)((warpN * 64 + (lane & 7) + ((lane >> 4) << 3)) * 256);
    const uint32_t sw     = (uint32_t)(lane & 7);
    const uint32_t achsel = (uint32_t)(lane >> 4);
    const uint32_t bchsel = (uint32_t)((lane >> 3) & 1);

    const float INF = __int_as_float(0x7F800000);
    float k1[4], k2[4];
    #pragma unroll
    for (int i = 0; i < 4; i++) { k1[i] = INF; k2[i] = INF; }

    for (int c = 0; c < NC; c++) {
        CP_WAIT1();
        __syncthreads();
        const int buf = c & 1;
        float acc[2][8][4];
        #pragma unroll
        for (int mi = 0; mi < 2; mi++)
            #pragma unroll
            for (int ni = 0; ni < 8; ni++)
                #pragma unroll
                for (int j = 0; j < 4; j++) acc[mi][ni][j] = 0.f;

        const uint32_t Ab = sb + S1_A_H + aOff;
        const uint32_t Bb = sb + S1_B + buf * S1_BBUF + bOff;
        #pragma unroll
        for (int ks = 0; ks < 8; ks++) {
            const uint32_t ach = (((uint32_t)(2 * ks) + achsel) ^ sw) << 4;
            const uint32_t bch = (((uint32_t)(2 * ks) + bchsel) ^ sw) << 4;
            uint32_t a[2][4];
            ldsm_x4(a[0], Ab + ach);
            ldsm_x4(a[1], Ab + 4096 + ach);
            #pragma unroll
            for (int h = 0; h < 2; h++) {
                uint32_t b[2][4];
                ldsm_x4(b[0], Bb + (h * 2 + 0) * 4096 + bch);
                ldsm_x4(b[1], Bb + (h * 2 + 1) * 4096 + bch);
                #pragma unroll
                for (int mi = 0; mi < 2; mi++)
                    #pragma unroll
                    for (int s2 = 0; s2 < 4; s2++)
                        mma16816(acc[mi][h * 4 + s2], a[mi], &b[s2 >> 1][(s2 & 1) * 2]);
            }
        }

        {   // packed-key top-2 fold
            const float* csqs = reinterpret_cast<const float*>(smem + S1_CSQ)
                                + c * 128 + warpN * 64;
            const uint32_t cb = (uint32_t)(c * 128 + warpN * 64 + (lane & 3) * 2);
            #pragma unroll
            for (int ni = 0; ni < 8; ni++) {
                const int col = ni * 8 + (lane & 3) * 2;
                const float cs0 = csqs[col], cs1 = csqs[col + 1];
                const uint32_t code0 = cb + ni * 8, code1 = code0 + 1;
                #pragma unroll
                for (int mi = 0; mi < 2; mi++)
                    #pragma unroll
                    for (int rh = 0; rh < 2; rh++) {
                        const int p = mi * 2 + rh;
                        float f0 = packkey(fmaf(-2.f, acc[mi][ni][rh * 2],     cs0), code0);
                        float f1 = packkey(fmaf(-2.f, acc[mi][ni][rh * 2 + 1], cs1), code1);
                        float m0 = fminf(k1[p], f0);
                        k2[p] = fminf(fmaxf(k1[p], f0), k2[p]);
                        k1[p] = m0;
                        float m1 = fminf(k1[p], f1);
                        k2[p] = fminf(fmaxf(k1[p], f1), k2[p]);
                        k1[p] = m1;
                    }
            }
        }

        __syncthreads();
        if (c + 2 < NC) s1_issue(sb, buf, c + 2, tid);
        CP_COMMIT();
    }

    CP_WAIT0();
    __syncthreads();

    #pragma unroll
    for (int mi = 0; mi < 2; mi++)
        #pragma unroll
        for (int rh = 0; rh < 2; rh++) {
            const int rowl = warpM * 32 + mi * 16 + rh * 8 + (lane >> 2);
            const int slot = warpN * 4 + (lane & 3);
            reinterpret_cast<float*>(smem + S1_REDK1)[rowl * 8 + slot] = k1[mi * 2 + rh];
            reinterpret_cast<float*>(smem + S1_REDK2)[rowl * 8 + slot] = k2[mi * 2 + rh];
        }
    __syncthreads();

    if (tid < BM) {
        const float* r1 = reinterpret_cast<const float*>(smem + S1_REDK1) + tid * 8;
        const float* r2 = reinterpret_cast<const float*>(smem + S1_REDK2) + tid * 8;
        float K1 = r1[0], K2 = r2[0];
        #pragma unroll
        for (int s = 1; s < 8; s++) {
            float a1 = r1[s], a2 = r2[s];
            float n1 = fminf(K1, a1);
            K2 = fminf(fminf(K2, a2), fmaxf(K1, a1));
            K1 = n1;
        }
        const int bi = (int)(__float_as_uint(K1) & 1023u);
        const int row = block_row + tid;
        const float xsqv   = reinterpret_cast<float*>(smem + S1_XSQ)[tid];
        const float xlosq  = reinterpret_cast<float*>(smem + S1_XLO)[tid];
        const float maxc   = reinterpret_cast<float*>(smem + S1_SCAL)[0];
        const float maxclo = reinterpret_cast<float*>(smem + S1_SCAL)[1];
        // exact-norm Cauchy-Schwarz certificate:
        //   per-score err <= 2(||x_lo||*||c|| + ||x_h||*||c_lo||); gap uses 2 scores
        const float xlo = sqrtf(xlosq);
        const float xh  = sqrtf(xsqv) + xlo;
        float analog = 4.f * (xlo * maxc + xh * maxclo);
        float pert   = 2.5e-4f * (fabsf(K1) + fabsf(K2)) + 0.03f;  // key-mask + accum slack
        float thresh = analog * 1.05f + pert;
        g_bi[row] = bi;
        if ((K2 - K1) <= thresh) {
            int pos = atomicAdd(&g_nflag, 1);
            g_list[pos] = row;
        }
    }
}

// ---------------- fallback: 3-pass split mma, 128 rows per tile ----------------
__device__ __forceinline__ void fb_issue(uint32_t sb, int buf, int chunk, int tid) {
    const char* src = (const char*)g_B + (size_t)chunk * 65536 + tid * 16;  // hi+lo
    uint32_t dst = sb + FB_B + buf * FB_BBUF + tid * 16;
    #pragma unroll
    for (int i = 0; i < 16; i++)
        CP_ASYNC16(dst + i * 4096, src + i * 4096);
}

__global__ __launch_bounds__(256, 1)
void vq_fb(const float* __restrict__ X, int n_codes)
{
    extern __shared__ char smem[];
    const uint32_t sb = smem_u32(smem);
    const int tid = threadIdx.x, lane = tid & 31, wid = tid >> 5;
    const int warpM = wid >> 1, warpN = wid & 1;      // 4x2 grid, 32x64 tiles
    const int NC = n_codes >> 7;
    const int Nf = g_nflag;

    for (int tile = blockIdx.x; tile * 128 < Nf; tile += gridDim.x) {
        CP_WAIT0();
        __syncthreads();
        if (tid < 128) {
            int idx = tile * 128 + tid;
            reinterpret_cast<int*>(smem + FB_RID)[tid] = g_list[idx < Nf ? idx : Nf - 1];
        }
        __syncthreads();

        {
            const int j = tid >> 1, h = tid & 1;
            const int srow = reinterpret_cast<int*>(smem + FB_RID)[j];
            const float4* src = reinterpret_cast<const float4*>(
                X + (size_t)srow * C_DIM + h * 64);
            #pragma unroll
            for (int q = 0; q < 16; q += 2) {
                float4 v0 = src[q], v1 = src[q + 1];
                uint4 H, L;
                split2(v0.x, v0.y, H.x, L.x); split2(v0.z, v0.w, H.y, L.y);
                split2(v1.x, v1.y, H.z, L.z); split2(v1.z, v1.w, H.w, L.w);
                int cg = h * 8 + (q >> 1);
                uint32_t off = (uint32_t)(j * 256 + ((cg ^ (j & 7)) << 4));
                *reinterpret_cast<uint4*>(smem + FB_A_H + off) = H;
                *reinterpret_cast<uint4*>(smem + FB_A_L + off) = L;
            }
        }
        __syncthreads();

        fb_issue(sb, 0, 0, tid);  CP_COMMIT();
        fb_issue(sb, 1, 1, tid);  CP_COMMIT();

        const uint32_t aOff   = (uint32_t)((warpM * 32 + (lane & 15)) * 256);
        const uint32_t bOff   = (uint32_t)((warpN * 64 + (lane & 7) + ((lane >> 4) << 3)) * 256);
        const uint32_t sw     = (uint32_t)(lane & 7);
        const uint32_t achsel = (uint32_t)(lane >> 4);
        const uint32_t bchsel = (uint32_t)((lane >> 3) & 1);

        float bestv[4];
        int   besti[4];
        #pragma unroll
        for (int i = 0; i < 4; i++) { bestv[i] = 3.4e38f; besti[i] = 0; }

        for (int c = 0; c < NC; c++) {
            CP_WAIT1();
            __syncthreads();
            const int buf = c & 1;
            float acc[2][8][4];
            #pragma unroll
            for (int mi = 0; mi < 2; mi++)
                #pragma unroll
                for (int ni = 0; ni < 8; ni++)
                    #pragma unroll
                    for (int j2 = 0; j2 < 4; j2++) acc[mi][ni][j2] = 0.f;

            #pragma unroll
            for (int pass = 0; pass < 3; pass++) {
                const uint32_t Ab = sb + (pass == 2 ? FB_A_L : FB_A_H) + aOff;
                const uint32_t Bb = sb + FB_B + buf * FB_BBUF + (pass == 1 ? 32768 : 0) + bOff;
                #pragma unroll
                for (int ks = 0; ks < 8; ks++) {
                    const uint32_t ach = (((uint32_t)(2 * ks) + achsel) ^ sw) << 4;
                    const uint32_t bch = (((uint32_t)(2 * ks) + bchsel) ^ sw) << 4;
                    uint32_t a[2][4], b[4][4];
                    ldsm_x4(a[0], Ab + ach);
                    ldsm_x4(a[1], Ab + 4096 + ach);
                    #pragma unroll
                    for (int nf2 = 0; nf2 < 4; nf2++)
                        ldsm_x4(b[nf2], Bb + nf2 * 4096 + bch);
                    #pragma unroll
                    for (int mi = 0; mi < 2; mi++)
                        #pragma unroll
                        for (int ni = 0; ni < 8; ni++)
                            mma16816(acc[mi][ni], a[mi], &b[ni >> 1][(ni & 1) * 2]);
                }
            }

            #pragma unroll
            for (int mi = 0; mi < 2; mi++)
                #pragma unroll
                for (int ni = 0; ni < 8; ni++) {
                    const int col = ni * 8 + (lane & 3) * 2;
                    const int gcol = c * 128 + warpN * 64 + col;
                    const float cs0 = __ldg(&g_csq[gcol]), cs1 = __ldg(&g_csq[gcol + 1]);
                    #pragma unroll
                    for (int rh = 0; rh < 2; rh++) {
                        const int p = mi * 2 + rh;
                        float v0 = fmaf(-2.f, acc[mi][ni][rh * 2],     cs0);
                        float v1 = fmaf(-2.f, acc[mi][ni][rh * 2 + 1], cs1);
                        if (v0 < bestv[p]) { bestv[p] = v0; besti[p] = gcol; }
                        if (v1 < bestv[p]) { bestv[p] = v1; besti[p] = gcol + 1; }
                    }
                }

            __syncthreads();
            if (c + 2 < NC) fb_issue(sb, buf, c + 2, tid);
            CP_COMMIT();
        }

        CP_WAIT0();
        __syncthreads();

        #pragma unroll
        for (int mi = 0; mi < 2; mi++)
            #pragma unroll
            for (int rh = 0; rh < 2; rh++) {
                const int rowl = warpM * 32 + mi * 16 + rh * 8 + (lane >> 2);
                const int slot = warpN * 4 + (lane & 3);
                reinterpret_cast<float*>(smem + FB_REDV)[rowl * 8 + slot] = bestv[mi * 2 + rh];
                reinterpret_cast<int*>(smem + FB_REDI)[rowl * 8 + slot]   = besti[mi * 2 + rh];
            }
        __syncthreads();

        if (tid < 128) {
            const float* rv = reinterpret_cast<const float*>(smem + FB_REDV) + tid * 8;
            const int*   ri = reinterpret_cast<const int*>(smem + FB_REDI) + tid * 8;
            float bv = rv[0]; int bi = ri[0];
            #pragma unroll
            for (int s = 1; s < 8; s++) {
                float v = rv[s]; int ii = ri[s];
                if (v < bv || (v == bv && ii < bi)) { bv = v; bi = ii; }
            }
            g_bi[reinterpret_cast<int*>(smem + FB_RID)[tid]] = bi;
        }
        __syncthreads();
    }
}

// ---------------- finish: exact fp32 distances + gather ----------------
__global__ __launch_bounds__(256, 4)
void vq_finish(const float* __restrict__ X, const float* __restrict__ CB,
               float* __restrict__ out_codes, float* __restrict__ out_fidx,
               float* __restrict__ out_idx,   float* __restrict__ out_dist)
{
    const int warp = threadIdx.x >> 5, lane = threadIdx.x & 31;
    const int row = blockIdx.x * 8 + warp;

    const int bi = g_bi[row];
    float4 xv = reinterpret_cast<const float4*>(X + (size_t)row * C_DIM)[lane];
    float4 cv = reinterpret_cast<const float4*>(CB + (size_t)bi * C_DIM)[lane];

    float xsq = xv.x*xv.x + xv.y*xv.y + xv.z*xv.z + xv.w*xv.w;
    float dot = cv.x*xv.x + cv.y*xv.y + cv.z*xv.z + cv.w*xv.w;
    #pragma unroll
    for (int o = 16; o; o >>= 1) {
        xsq += __shfl_xor_sync(0xffffffffu, xsq, o);
        dot += __shfl_xor_sync(0xffffffffu, dot, o);
    }

    if (lane == 0 && out_fidx) {
        float fbi = (float)bi;
        out_fidx[row] = fbi;
        out_idx[row]  = fbi;
        out_dist[row] = xsq + fmaf(-2.f, dot, g_csq[bi]);
    }
    reinterpret_cast<float4*>(out_codes + (size_t)row * C_DIM)[lane] = cv;
}

extern "C" void kernel_launch(void* const* d_in, const int* in_sizes, int n_in,
                              void* d_out, int out_size)
{
    const float* X  = (const float*)d_in[0];
    const float* CB = (const float*)d_in[1];
    float* out = (float*)d_out;

    const int n_rows  = in_sizes[0] / C_DIM;   // 65536
    const int n_codes = in_sizes[1] / C_DIM;   // 1024

    size_t codes_n = (size_t)n_rows * C_DIM;
    bool extras = ((size_t)out_size >= codes_n + 3 * (size_t)n_rows);

    float* out_codes = out;
    float* out_fidx  = extras ? out + codes_n : nullptr;
    float* out_idx   = extras ? out + codes_n + n_rows : nullptr;
    float* out_dist  = extras ? out + codes_n + 2 * (size_t)n_rows : nullptr;

    static bool attr_set = false;
    if (!attr_set) {
        cudaFuncSetAttribute(vq_stage1, cudaFuncAttributeMaxDynamicSharedMemorySize, S1_SMEM);
        cudaFuncSetAttribute(vq_fb,     cudaFuncAttributeMaxDynamicSharedMemorySize, FB_SMEM);
        attr_set = true;
    }

    prep_cb<<<(n_codes * 2) / 256, 256>>>(CB);
    vq_stage1<<<n_rows / BM, 256, S1_SMEM>>>(X, n_codes);
    vq_fb<<<64, 256, FB_SMEM>>>(X, n_codes);
    vq_finish<<<n_rows / 8, 256>>>(X, CB, out_codes, out_fidx, out_idx, out_dist);
}